// round 14
// baseline (speedup 1.0000x reference)
#include <cuda_runtime.h>
#include <cuda_fp16.h>
#include <cstdint>

#define NBLK 8
#define CH 256
#define ROWSTRIDE 2048
#define OUT_HALF 33554432u

#define NSIGN 0x80008000u

// smem: bias 2KB | W_r 34816B (32 rows x 1088) | W_i 34816B
#define SMEM_WR   2048
#define SMEM_WI   (2048 + 34816)
#define SMEM_ALLOC (2048 + 2*34816)      // 71680 -> 2 CTA/SM

// fp16 weights, fragment-permuted per (sel,blk):
// byte offset = rowg*1024 + s*64 + t*16 + h*8 + j*2
//   n = (rowg>>3)*16 + h*8 + (rowg&7),  k = s*16 + t*4 + j
__device__ __half g_wT[2*NBLK*CH*CH];

// ---------------------------------------------------------------------------
__device__ __forceinline__ uint32_t smem_u32(const void* p){
    uint32_t r;
    asm("{ .reg .u64 t; cvta.to.shared.u64 t, %1; cvt.u32.u64 %0, t; }"
        : "=r"(r) : "l"(p));
    return r;
}
__device__ __forceinline__ void cpa16(uint32_t dst, const void* src){
    asm volatile("cp.async.cg.shared.global [%0], [%1], 16;"
                 :: "r"(dst), "l"(src) : "memory");
}
__device__ __forceinline__ void cp_commit(){ asm volatile("cp.async.commit_group;" ::: "memory"); }
__device__ __forceinline__ void cp_wait0(){ asm volatile("cp.async.wait_group 0;" ::: "memory"); }

__device__ __forceinline__ void lds128(uint32_t a, uint32_t* v){
    asm volatile("ld.shared.v4.b32 {%0,%1,%2,%3}, [%4];"
        : "=r"(v[0]), "=r"(v[1]), "=r"(v[2]), "=r"(v[3]) : "r"(a));
}
__device__ __forceinline__ uint32_t packh2(float x, float y){
    __half2 h = __floats2half2_rn(x, y);
    return *(uint32_t*)&h;
}
__device__ __forceinline__ void mma16(float* d, const uint32_t* a,
                                      uint32_t b0, uint32_t b1){
    asm volatile(
        "mma.sync.aligned.m16n8k16.row.col.f32.f16.f16.f32 "
        "{%0,%1,%2,%3}, {%4,%5,%6,%7}, {%8,%9}, {%0,%1,%2,%3};"
        : "+f"(d[0]), "+f"(d[1]), "+f"(d[2]), "+f"(d[3])
        : "r"(a[0]), "r"(a[1]), "r"(a[2]), "r"(a[3]), "r"(b0), "r"(b1));
}
// streaming store (evict-first): don't let dead output displace A in L2
__device__ __forceinline__ void stg_cs_f2(float* p, float x, float y){
    asm volatile("st.global.cs.v2.f32 [%0], {%1,%2};"
                 :: "l"(p), "f"(x), "f"(y) : "memory");
}

// ---------------------------------------------------------------------------
// Prep: w[b][d][n] fp32 -> g_wT permuted fp16
// ---------------------------------------------------------------------------
__global__ void emm_prep(const float* __restrict__ wr, const float* __restrict__ wi){
    int bb = blockIdx.x;                 // sel*8 + b
    int s  = blockIdx.y;                 // k-slice 0..15
    const float* src = (bb >= 8 ? wi : wr) + (size_t)(bb & 7)*CH*CH;
    char* dst = (char*)g_wT + (size_t)bb*CH*CH*2;
    int n = threadIdx.x;                 // 0..255
    int rowg = (n >> 4)*8 + (n & 7);
    int h = (n >> 3) & 1;
    #pragma unroll
    for (int t = 0; t < 4; t++){
        int d = s*16 + t*4;
        uint2 v;
        v.x = packh2(src[(size_t)d*CH + n],     src[(size_t)(d+1)*CH + n]);
        v.y = packh2(src[(size_t)(d+2)*CH + n], src[(size_t)(d+3)*CH + n]);
        *(uint2*)(dst + rowg*1024 + s*64 + t*16 + h*8) = v;
    }
}

// ---------------------------------------------------------------------------
// 8 MMAs for one q (n-subtile pair), W fragment buffer WB
// ---------------------------------------------------------------------------
#define MMAQ(q, WB) do { \
    mma16(dr[2*(q)],   far, wfr[WB][0], wfr[WB][1]); \
    mma16(dr[2*(q)+1], far, wfr[WB][2], wfr[WB][3]); \
    mma16(di[2*(q)],   far, wfi[WB][0], wfi[WB][1]); \
    mma16(di[2*(q)+1], far, wfi[WB][2], wfi[WB][3]); \
    mma16(dr[2*(q)],   fan, wfi[WB][0], wfi[WB][1]); \
    mma16(dr[2*(q)+1], fan, wfi[WB][2], wfi[WB][3]); \
    mma16(di[2*(q)],   fai, wfr[WB][0], wfr[WB][1]); \
    mma16(di[2*(q)+1], fai, wfr[WB][2], wfr[WB][3]); \
} while(0)

// one slice of 32 MMAs + W-fragment ping-pong; advances wro/wio
#define SLICE_MMA() do { \
    lds128(wro + 8704,   wfr[1]); \
    lds128(wio + 8704,   wfi[1]); \
    MMAQ(0, 0); \
    lds128(wro + 2*8704, wfr[0]); \
    lds128(wio + 2*8704, wfi[0]); \
    MMAQ(1, 1); \
    lds128(wro + 3*8704, wfr[1]); \
    lds128(wio + 3*8704, wfi[1]); \
    MMAQ(2, 0); \
    lds128(wro + 64, wfr[0]); \
    lds128(wio + 64, wfi[0]); \
    MMAQ(3, 1); \
    wro += 64; wio += 64; \
} while(0)

// pack next slice's fragments from the raw buffer (LDG'd one slice ago)
#define PACK_NEXT() do { \
    far[0] = packh2(rR0.x, rR0.y); far[1] = packh2(rR1.x, rR1.y); \
    far[2] = packh2(rR0.z, rR0.w); far[3] = packh2(rR1.z, rR1.w); \
    fai[0] = packh2(rI0.x, rI0.y); fai[1] = packh2(rI1.x, rI1.y); \
    fai[2] = packh2(rI0.z, rI0.w); fai[3] = packh2(rI1.z, rI1.w); \
    fan[0] = fai[0]^NSIGN; fan[1] = fai[1]^NSIGN; \
    fan[2] = fai[2]^NSIGN; fan[3] = fai[3]^NSIGN; \
} while(0)

#define LDG_AHEAD(o) do { \
    rR0 = *(const float4*)(pr0 + (o)); \
    rR1 = *(const float4*)(pr0 + (o) + 8*ROWSTRIDE); \
    rI0 = *(const float4*)(pi0 + (o)); \
    rI1 = *(const float4*)(pi0 + (o) + 8*ROWSTRIDE); \
} while(0)

// ---------------------------------------------------------------------------
__global__ void __launch_bounds__(256, 2) emm_main(
    const float* __restrict__ xr, const float* __restrict__ xi,
    const float* __restrict__ br, const float* __restrict__ bi,
    float* __restrict__ out)
{
    extern __shared__ char smem[];
    uint32_t sb = smem_u32(smem);
    int tid = threadIdx.x;
    int wid = tid >> 5, lid = tid & 31;
    int g = lid >> 2, t = lid & 3;

    int bx = blockIdx.x;
    int m0 = (bx >> 2) * 128;            // adjacent bx share m0 -> L2 reuse
    int n0 = (bx & 3) * 64;
    int blk = blockIdx.y;

    const float* pr0 = xr + (size_t)(m0 + wid*16 + g)*ROWSTRIDE + blk*CH + t*4;
    const float* pi0 = xi + (size_t)(m0 + wid*16 + g)*ROWSTRIDE + blk*CH + t*4;

    // slice-0 A loads (hide behind W smem fill)
    float4 rR0 = *(const float4*)pr0;
    float4 rR1 = *(const float4*)(pr0 + 8*ROWSTRIDE);
    float4 rI0 = *(const float4*)pi0;
    float4 rI1 = *(const float4*)(pi0 + 8*ROWSTRIDE);

    // bias -> smem
    float* bs = (float*)smem;
    bs[tid]       = br[blk*CH + tid];
    bs[tid + 256] = bi[blk*CH + tid];

    // W -> smem once: 2048 16B chunks per tensor, rows padded 1024 -> 1088
    {
        const char* wr_src = (const char*)g_wT + (size_t)blk*131072 + (size_t)n0*512;
        const char* wi_src = wr_src + (size_t)NBLK*131072;
        #pragma unroll
        for (int i = 0; i < 8; i++){
            int c = tid + i*256;         // 0..2047
            uint32_t d = (uint32_t)((c >> 6)*1088 + (c & 63)*16);
            cpa16(sb + SMEM_WR + d, wr_src + (size_t)c*16);
            cpa16(sb + SMEM_WI + d, wi_src + (size_t)c*16);
        }
        cp_commit();
    }

    float dr[8][4], di[8][4];
    #pragma unroll
    for (int n = 0; n < 8; n++)
        #pragma unroll
        for (int c = 0; c < 4; c++){ dr[n][c] = 0.f; di[n][c] = 0.f; }

    cp_wait0();
    __syncthreads();                     // the ONLY barrier before epilogue

    // pack slice-0 fragments
    uint32_t far[4], fai[4], fan[4];
    PACK_NEXT();

    // issue slice-1 A loads
    LDG_AHEAD(16);

    uint32_t wro = sb + SMEM_WR + (uint32_t)(g*1088 + t*16);
    uint32_t wio = sb + SMEM_WI + (uint32_t)(g*1088 + t*16);

    // preload W fragments for (j=0, q=0)
    uint32_t wfr[2][4], wfi[2][4];
    lds128(wro, wfr[0]);
    lds128(wio, wfi[0]);

    // slices 0..13: branch-free hot loop (pack j+1, LDG j+2)
    #pragma unroll 1
    for (int j = 0; j < 14; j++){
        SLICE_MMA();
        PACK_NEXT();
        LDG_AHEAD((j + 2) * 16);
    }
    // slice 14: pack slice 15, no LDG
    SLICE_MMA();
    PACK_NEXT();
    // slice 15: MMAs only
    SLICE_MMA();

    // epilogue: bias + coalesced float2 streaming stores (evict-first)
    float* o_r = out;
    float* o_i = out + OUT_HALF;
    int row0 = m0 + wid*16 + g;
    #pragma unroll
    for (int nn = 0; nn < 8; nn++){
        int cidx = n0 + nn*8 + 2*t;
        size_t col = (size_t)blk*CH + cidx;
        float b0r = bs[cidx], b1r = bs[cidx+1];
        float b0i = bs[256+cidx], b1i = bs[256+cidx+1];
        size_t a0 = (size_t)row0 * ROWSTRIDE + col;
        size_t a1 = (size_t)(row0 + 8) * ROWSTRIDE + col;
        stg_cs_f2(o_r + a0, dr[nn][0] + b0r, dr[nn][1] + b1r);
        stg_cs_f2(o_r + a1, dr[nn][2] + b0r, dr[nn][3] + b1r);
        stg_cs_f2(o_i + a0, di[nn][0] + b0i, di[nn][1] + b1i);
        stg_cs_f2(o_i + a1, di[nn][2] + b0i, di[nn][3] + b1i);
    }
}

// ---------------------------------------------------------------------------
extern "C" void kernel_launch(void* const* d_in, const int* in_sizes, int n_in,
                              void* d_out, int out_size)
{
    const float* real = (const float*)d_in[0];
    const float* imag = (const float*)d_in[1];
    const float* w_r  = (const float*)d_in[2];
    const float* w_i  = (const float*)d_in[3];
    const float* b_r  = (const float*)d_in[4];
    const float* b_i  = (const float*)d_in[5];
    float* out = (float*)d_out;

    cudaFuncSetAttribute(emm_main,
        cudaFuncAttributeMaxDynamicSharedMemorySize, SMEM_ALLOC);

    emm_prep<<<dim3(16, 16), 256>>>(w_r, w_i);
    emm_main<<<dim3(512, 8), 256, SMEM_ALLOC>>>(real, imag, b_r, b_i, out);
}

// round 15
// speedup vs baseline: 1.0092x; 1.0092x over previous
#include <cuda_runtime.h>
#include <cuda_fp16.h>
#include <cstdint>

#define NBLK 8
#define CH 256
#define ROWSTRIDE 2048
#define OUT_HALF 33554432u

#define NSIGN 0x80008000u

// smem: bias 2KB | W_r 34816B (32 rows x 1088) | W_i 34816B
#define SMEM_WR   2048
#define SMEM_WI   (2048 + 34816)
#define SMEM_ALLOC (2048 + 2*34816)      // 71680 -> 2 CTA/SM

// fp16 weights, fragment-permuted per (sel,blk):
// byte offset = rowg*1024 + s*64 + t*16 + h*8 + j*2
//   n = (rowg>>3)*16 + h*8 + (rowg&7),  k = s*16 + t*4 + j
__device__ __half g_wT[2*NBLK*CH*CH];

// ---------------------------------------------------------------------------
__device__ __forceinline__ uint32_t smem_u32(const void* p){
    uint32_t r;
    asm("{ .reg .u64 t; cvta.to.shared.u64 t, %1; cvt.u32.u64 %0, t; }"
        : "=r"(r) : "l"(p));
    return r;
}
__device__ __forceinline__ void cpa16(uint32_t dst, const void* src){
    asm volatile("cp.async.cg.shared.global [%0], [%1], 16;"
                 :: "r"(dst), "l"(src) : "memory");
}
__device__ __forceinline__ void cp_commit(){ asm volatile("cp.async.commit_group;" ::: "memory"); }
__device__ __forceinline__ void cp_wait0(){ asm volatile("cp.async.wait_group 0;" ::: "memory"); }

__device__ __forceinline__ void lds128(uint32_t a, uint32_t* v){
    asm volatile("ld.shared.v4.b32 {%0,%1,%2,%3}, [%4];"
        : "=r"(v[0]), "=r"(v[1]), "=r"(v[2]), "=r"(v[3]) : "r"(a));
}
__device__ __forceinline__ uint32_t packh2(float x, float y){
    __half2 h = __floats2half2_rn(x, y);
    return *(uint32_t*)&h;
}
__device__ __forceinline__ void mma16(float* d, const uint32_t* a,
                                      uint32_t b0, uint32_t b1){
    asm volatile(
        "mma.sync.aligned.m16n8k16.row.col.f32.f16.f16.f32 "
        "{%0,%1,%2,%3}, {%4,%5,%6,%7}, {%8,%9}, {%0,%1,%2,%3};"
        : "+f"(d[0]), "+f"(d[1]), "+f"(d[2]), "+f"(d[3])
        : "r"(a[0]), "r"(a[1]), "r"(a[2]), "r"(a[3]), "r"(b0), "r"(b1));
}
// streaming store (evict-first): don't let dead output displace A in L2
__device__ __forceinline__ void stg_cs_f2(float* p, float x, float y){
    asm volatile("st.global.cs.v2.f32 [%0], {%1,%2};"
                 :: "l"(p), "f"(x), "f"(y) : "memory");
}

// ---------------------------------------------------------------------------
// Prep v2: w[b][d][n] fp32 -> g_wT permuted fp16, SMEM-staged so all
// global writes are full 16B chunks inside fully-written 32B sectors.
// block (bb, s): 256 threads, stage 128 rowg x 64B (padded to 80B/rowg).
// ---------------------------------------------------------------------------
__global__ void emm_prep(const float* __restrict__ wr, const float* __restrict__ wi){
    __shared__ char stg[128 * 80];       // 10240 B
    int bb = blockIdx.x;                 // sel*8 + b
    int s  = blockIdx.y;                 // k-slice 0..15
    const float* src = (bb >= 8 ? wi : wr) + (size_t)(bb & 7)*CH*CH;
    char* dst = (char*)g_wT + (size_t)bb*CH*CH*2;
    int n = threadIdx.x;                 // 0..255
    int rowg = (n >> 4)*8 + (n & 7);     // 0..127
    int h = (n >> 3) & 1;
    #pragma unroll
    for (int t = 0; t < 4; t++){
        int d = s*16 + t*4;
        uint2 v;
        v.x = packh2(src[(size_t)d*CH + n],     src[(size_t)(d+1)*CH + n]);
        v.y = packh2(src[(size_t)(d+2)*CH + n], src[(size_t)(d+3)*CH + n]);
        *(uint2*)(stg + rowg*80 + t*16 + h*8) = v;
    }
    __syncthreads();
    #pragma unroll
    for (int k = 0; k < 2; k++){
        int idx = threadIdx.x + k*256;   // 0..511
        int rg = idx >> 2, c = idx & 3;
        *(uint4*)(dst + rg*1024 + s*64 + c*16) =
            *(const uint4*)(stg + rg*80 + c*16);
    }
}

// ---------------------------------------------------------------------------
// 8 MMAs for one q (n-subtile pair), W fragment buffer WB
// ---------------------------------------------------------------------------
#define MMAQ(q, WB) do { \
    mma16(dr[2*(q)],   far, wfr[WB][0], wfr[WB][1]); \
    mma16(dr[2*(q)+1], far, wfr[WB][2], wfr[WB][3]); \
    mma16(di[2*(q)],   far, wfi[WB][0], wfi[WB][1]); \
    mma16(di[2*(q)+1], far, wfi[WB][2], wfi[WB][3]); \
    mma16(dr[2*(q)],   fan, wfi[WB][0], wfi[WB][1]); \
    mma16(dr[2*(q)+1], fan, wfi[WB][2], wfi[WB][3]); \
    mma16(di[2*(q)],   fai, wfr[WB][0], wfr[WB][1]); \
    mma16(di[2*(q)+1], fai, wfr[WB][2], wfr[WB][3]); \
} while(0)

// one slice of 32 MMAs + W-fragment ping-pong; advances wro/wio
#define SLICE_MMA() do { \
    lds128(wro + 8704,   wfr[1]); \
    lds128(wio + 8704,   wfi[1]); \
    MMAQ(0, 0); \
    lds128(wro + 2*8704, wfr[0]); \
    lds128(wio + 2*8704, wfi[0]); \
    MMAQ(1, 1); \
    lds128(wro + 3*8704, wfr[1]); \
    lds128(wio + 3*8704, wfi[1]); \
    MMAQ(2, 0); \
    lds128(wro + 64, wfr[0]); \
    lds128(wio + 64, wfi[0]); \
    MMAQ(3, 1); \
    wro += 64; wio += 64; \
} while(0)

// pack next slice's fragments from the raw buffer (LDG'd one slice ago)
#define PACK_NEXT() do { \
    far[0] = packh2(rR0.x, rR0.y); far[1] = packh2(rR1.x, rR1.y); \
    far[2] = packh2(rR0.z, rR0.w); far[3] = packh2(rR1.z, rR1.w); \
    fai[0] = packh2(rI0.x, rI0.y); fai[1] = packh2(rI1.x, rI1.y); \
    fai[2] = packh2(rI0.z, rI0.w); fai[3] = packh2(rI1.z, rI1.w); \
    fan[0] = fai[0]^NSIGN; fan[1] = fai[1]^NSIGN; \
    fan[2] = fai[2]^NSIGN; fan[3] = fai[3]^NSIGN; \
} while(0)

#define LDG_AHEAD(o) do { \
    rR0 = *(const float4*)(pr0 + (o)); \
    rR1 = *(const float4*)(pr0 + (o) + 8*ROWSTRIDE); \
    rI0 = *(const float4*)(pi0 + (o)); \
    rI1 = *(const float4*)(pi0 + (o) + 8*ROWSTRIDE); \
} while(0)

// ---------------------------------------------------------------------------
__global__ void __launch_bounds__(256, 2) emm_main(
    const float* __restrict__ xr, const float* __restrict__ xi,
    const float* __restrict__ br, const float* __restrict__ bi,
    float* __restrict__ out)
{
    extern __shared__ char smem[];
    uint32_t sb = smem_u32(smem);
    int tid = threadIdx.x;
    int wid = tid >> 5, lid = tid & 31;
    int g = lid >> 2, t = lid & 3;

    int bx = blockIdx.x;
    int m0 = (bx >> 2) * 128;            // adjacent bx share m0 -> L2 reuse
    int n0 = (bx & 3) * 64;
    int blk = blockIdx.y;

    const float* pr0 = xr + (size_t)(m0 + wid*16 + g)*ROWSTRIDE + blk*CH + t*4;
    const float* pi0 = xi + (size_t)(m0 + wid*16 + g)*ROWSTRIDE + blk*CH + t*4;

    // slice-0 A loads (hide behind W smem fill)
    float4 rR0 = *(const float4*)pr0;
    float4 rR1 = *(const float4*)(pr0 + 8*ROWSTRIDE);
    float4 rI0 = *(const float4*)pi0;
    float4 rI1 = *(const float4*)(pi0 + 8*ROWSTRIDE);

    // bias -> smem
    float* bs = (float*)smem;
    bs[tid]       = br[blk*CH + tid];
    bs[tid + 256] = bi[blk*CH + tid];

    // W -> smem once: 2048 16B chunks per tensor, rows padded 1024 -> 1088
    {
        const char* wr_src = (const char*)g_wT + (size_t)blk*131072 + (size_t)n0*512;
        const char* wi_src = wr_src + (size_t)NBLK*131072;
        #pragma unroll
        for (int i = 0; i < 8; i++){
            int c = tid + i*256;         // 0..2047
            uint32_t d = (uint32_t)((c >> 6)*1088 + (c & 63)*16);
            cpa16(sb + SMEM_WR + d, wr_src + (size_t)c*16);
            cpa16(sb + SMEM_WI + d, wi_src + (size_t)c*16);
        }
        cp_commit();
    }

    float dr[8][4], di[8][4];
    #pragma unroll
    for (int n = 0; n < 8; n++)
        #pragma unroll
        for (int c = 0; c < 4; c++){ dr[n][c] = 0.f; di[n][c] = 0.f; }

    cp_wait0();
    __syncthreads();                     // the ONLY barrier before epilogue

    // pack slice-0 fragments
    uint32_t far[4], fai[4], fan[4];
    PACK_NEXT();

    // issue slice-1 A loads
    LDG_AHEAD(16);

    uint32_t wro = sb + SMEM_WR + (uint32_t)(g*1088 + t*16);
    uint32_t wio = sb + SMEM_WI + (uint32_t)(g*1088 + t*16);

    // preload W fragments for (j=0, q=0)
    uint32_t wfr[2][4], wfi[2][4];
    lds128(wro, wfr[0]);
    lds128(wio, wfi[0]);

    // slices 0..13: branch-free hot loop (pack j+1, LDG j+2)
    #pragma unroll 1
    for (int j = 0; j < 14; j++){
        SLICE_MMA();
        PACK_NEXT();
        LDG_AHEAD((j + 2) * 16);
    }
    // slice 14: pack slice 15, no LDG
    SLICE_MMA();
    PACK_NEXT();
    // slice 15: MMAs only
    SLICE_MMA();

    // epilogue: bias + coalesced float2 streaming stores (evict-first)
    float* o_r = out;
    float* o_i = out + OUT_HALF;
    int row0 = m0 + wid*16 + g;
    #pragma unroll
    for (int nn = 0; nn < 8; nn++){
        int cidx = n0 + nn*8 + 2*t;
        size_t col = (size_t)blk*CH + cidx;
        float b0r = bs[cidx], b1r = bs[cidx+1];
        float b0i = bs[256+cidx], b1i = bs[256+cidx+1];
        size_t a0 = (size_t)row0 * ROWSTRIDE + col;
        size_t a1 = (size_t)(row0 + 8) * ROWSTRIDE + col;
        stg_cs_f2(o_r + a0, dr[nn][0] + b0r, dr[nn][1] + b1r);
        stg_cs_f2(o_r + a1, dr[nn][2] + b0r, dr[nn][3] + b1r);
        stg_cs_f2(o_i + a0, di[nn][0] + b0i, di[nn][1] + b1i);
        stg_cs_f2(o_i + a1, di[nn][2] + b0i, di[nn][3] + b1i);
    }
}

// ---------------------------------------------------------------------------
extern "C" void kernel_launch(void* const* d_in, const int* in_sizes, int n_in,
                              void* d_out, int out_size)
{
    const float* real = (const float*)d_in[0];
    const float* imag = (const float*)d_in[1];
    const float* w_r  = (const float*)d_in[2];
    const float* w_i  = (const float*)d_in[3];
    const float* b_r  = (const float*)d_in[4];
    const float* b_i  = (const float*)d_in[5];
    float* out = (float*)d_out;

    cudaFuncSetAttribute(emm_main,
        cudaFuncAttributeMaxDynamicSharedMemorySize, SMEM_ALLOC);

    emm_prep<<<dim3(16, 16), 256>>>(w_r, w_i);
    emm_main<<<dim3(512, 8), 256, SMEM_ALLOC>>>(real, imag, b_r, b_i, out);
}

// round 16
// speedup vs baseline: 1.0110x; 1.0018x over previous
#include <cuda_runtime.h>
#include <cuda_fp16.h>
#include <cstdint>

#define NBLK 8
#define CH 256
#define ROWSTRIDE 2048
#define OUT_HALF 33554432u

#define NSIGN 0x80008000u

// smem: bias 2KB | W_r 34816B (32 rows x 1088) | W_i 34816B
#define SMEM_WR   2048
#define SMEM_WI   (2048 + 34816)
#define SMEM_ALLOC (2048 + 2*34816)      // 71680 -> 2 CTA/SM

// fp16 weights, fragment-permuted per (sel,blk):
// byte offset = rowg*1024 + s*64 + t*16 + h*8 + j*2
//   n = (rowg>>3)*16 + h*8 + (rowg&7),  k = s*16 + t*4 + j
__device__ __half g_wT[2*NBLK*CH*CH];

// ---------------------------------------------------------------------------
__device__ __forceinline__ uint32_t smem_u32(const void* p){
    uint32_t r;
    asm("{ .reg .u64 t; cvta.to.shared.u64 t, %1; cvt.u32.u64 %0, t; }"
        : "=r"(r) : "l"(p));
    return r;
}
__device__ __forceinline__ void cpa16(uint32_t dst, const void* src){
    asm volatile("cp.async.cg.shared.global [%0], [%1], 16;"
                 :: "r"(dst), "l"(src) : "memory");
}
__device__ __forceinline__ void cp_commit(){ asm volatile("cp.async.commit_group;" ::: "memory"); }
__device__ __forceinline__ void cp_wait0(){ asm volatile("cp.async.wait_group 0;" ::: "memory"); }

__device__ __forceinline__ void lds128(uint32_t a, uint32_t* v){
    asm volatile("ld.shared.v4.b32 {%0,%1,%2,%3}, [%4];"
        : "=r"(v[0]), "=r"(v[1]), "=r"(v[2]), "=r"(v[3]) : "r"(a));
}
__device__ __forceinline__ uint32_t packh2(float x, float y){
    __half2 h = __floats2half2_rn(x, y);
    return *(uint32_t*)&h;
}
__device__ __forceinline__ void mma16(float* d, const uint32_t* a,
                                      uint32_t b0, uint32_t b1){
    asm volatile(
        "mma.sync.aligned.m16n8k16.row.col.f32.f16.f16.f32 "
        "{%0,%1,%2,%3}, {%4,%5,%6,%7}, {%8,%9}, {%0,%1,%2,%3};"
        : "+f"(d[0]), "+f"(d[1]), "+f"(d[2]), "+f"(d[3])
        : "r"(a[0]), "r"(a[1]), "r"(a[2]), "r"(a[3]), "r"(b0), "r"(b1));
}
// streaming store (evict-first): don't let dead output displace A in L2
__device__ __forceinline__ void stg_cs_f2(float* p, float x, float y){
    asm volatile("st.global.cs.v2.f32 [%0], {%1,%2};"
                 :: "l"(p), "f"(x), "f"(y) : "memory");
}

// ---------------------------------------------------------------------------
// Prep v2: w[b][d][n] fp32 -> g_wT permuted fp16, SMEM-staged so all
// global writes are full 16B chunks inside fully-written 32B sectors.
// ---------------------------------------------------------------------------
__global__ void emm_prep(const float* __restrict__ wr, const float* __restrict__ wi){
    __shared__ char stg[128 * 80];       // 10240 B
    int bb = blockIdx.x;                 // sel*8 + b
    int s  = blockIdx.y;                 // k-slice 0..15
    const float* src = (bb >= 8 ? wi : wr) + (size_t)(bb & 7)*CH*CH;
    char* dst = (char*)g_wT + (size_t)bb*CH*CH*2;
    int n = threadIdx.x;                 // 0..255
    int rowg = (n >> 4)*8 + (n & 7);     // 0..127
    int h = (n >> 3) & 1;
    #pragma unroll
    for (int t = 0; t < 4; t++){
        int d = s*16 + t*4;
        uint2 v;
        v.x = packh2(src[(size_t)d*CH + n],     src[(size_t)(d+1)*CH + n]);
        v.y = packh2(src[(size_t)(d+2)*CH + n], src[(size_t)(d+3)*CH + n]);
        *(uint2*)(stg + rowg*80 + t*16 + h*8) = v;
    }
    __syncthreads();
    #pragma unroll
    for (int k = 0; k < 2; k++){
        int idx = threadIdx.x + k*256;   // 0..511
        int rg = idx >> 2, c = idx & 3;
        *(uint4*)(dst + rg*1024 + s*64 + c*16) =
            *(const uint4*)(stg + rg*80 + c*16);
    }
}

// ---------------------------------------------------------------------------
// 8 MMAs for one q (n-subtile pair), W fragment buffer WB
// ---------------------------------------------------------------------------
#define MMAQ(q, WB) do { \
    mma16(dr[2*(q)],   far, wfr[WB][0], wfr[WB][1]); \
    mma16(dr[2*(q)+1], far, wfr[WB][2], wfr[WB][3]); \
    mma16(di[2*(q)],   far, wfi[WB][0], wfi[WB][1]); \
    mma16(di[2*(q)+1], far, wfi[WB][2], wfi[WB][3]); \
    mma16(dr[2*(q)],   fan, wfi[WB][0], wfi[WB][1]); \
    mma16(dr[2*(q)+1], fan, wfi[WB][2], wfi[WB][3]); \
    mma16(di[2*(q)],   fai, wfr[WB][0], wfr[WB][1]); \
    mma16(di[2*(q)+1], fai, wfr[WB][2], wfr[WB][3]); \
} while(0)

// one slice of 32 MMAs + W-fragment ping-pong; advances wro/wio
#define SLICE_MMA() do { \
    lds128(wro + 8704,   wfr[1]); \
    lds128(wio + 8704,   wfi[1]); \
    MMAQ(0, 0); \
    lds128(wro + 2*8704, wfr[0]); \
    lds128(wio + 2*8704, wfi[0]); \
    MMAQ(1, 1); \
    lds128(wro + 3*8704, wfr[1]); \
    lds128(wio + 3*8704, wfi[1]); \
    MMAQ(2, 0); \
    lds128(wro + 64, wfr[0]); \
    lds128(wio + 64, wfi[0]); \
    MMAQ(3, 1); \
    wro += 64; wio += 64; \
} while(0)

// pack far from rR, then immediately re-issue rR loads (earlier LSU issue);
// then pack fai/fan from rI and re-issue rI loads.
#define PACK_R(o) do { \
    far[0] = packh2(rR0.x, rR0.y); far[1] = packh2(rR1.x, rR1.y); \
    far[2] = packh2(rR0.z, rR0.w); far[3] = packh2(rR1.z, rR1.w); \
    rR0 = *(const float4*)(pr0 + (o)); \
    rR1 = *(const float4*)(pr0 + (o) + 8*ROWSTRIDE); \
} while(0)
#define PACK_I(o) do { \
    fai[0] = packh2(rI0.x, rI0.y); fai[1] = packh2(rI1.x, rI1.y); \
    fai[2] = packh2(rI0.z, rI0.w); fai[3] = packh2(rI1.z, rI1.w); \
    fan[0] = fai[0]^NSIGN; fan[1] = fai[1]^NSIGN; \
    fan[2] = fai[2]^NSIGN; fan[3] = fai[3]^NSIGN; \
    rI0 = *(const float4*)(pi0 + (o)); \
    rI1 = *(const float4*)(pi0 + (o) + 8*ROWSTRIDE); \
} while(0)
#define PACK_ONLY() do { \
    far[0] = packh2(rR0.x, rR0.y); far[1] = packh2(rR1.x, rR1.y); \
    far[2] = packh2(rR0.z, rR0.w); far[3] = packh2(rR1.z, rR1.w); \
    fai[0] = packh2(rI0.x, rI0.y); fai[1] = packh2(rI1.x, rI1.y); \
    fai[2] = packh2(rI0.z, rI0.w); fai[3] = packh2(rI1.z, rI1.w); \
    fan[0] = fai[0]^NSIGN; fan[1] = fai[1]^NSIGN; \
    fan[2] = fai[2]^NSIGN; fan[3] = fai[3]^NSIGN; \
} while(0)

// ---------------------------------------------------------------------------
__global__ void __launch_bounds__(256, 2) emm_main(
    const float* __restrict__ xr, const float* __restrict__ xi,
    const float* __restrict__ br, const float* __restrict__ bi,
    float* __restrict__ out)
{
    extern __shared__ char smem[];
    uint32_t sb = smem_u32(smem);
    int tid = threadIdx.x;
    int wid = tid >> 5, lid = tid & 31;
    int g = lid >> 2, t = lid & 3;

    int bx = blockIdx.x;
    int m0 = (bx >> 2) * 128;            // adjacent bx share m0 -> L2 reuse
    int n0 = (bx & 3) * 64;
    int blk = blockIdx.y;

    const float* pr0 = xr + (size_t)(m0 + wid*16 + g)*ROWSTRIDE + blk*CH + t*4;
    const float* pi0 = xi + (size_t)(m0 + wid*16 + g)*ROWSTRIDE + blk*CH + t*4;

    // slice-0 A loads (hide behind W smem fill)
    float4 rR0 = *(const float4*)pr0;
    float4 rR1 = *(const float4*)(pr0 + 8*ROWSTRIDE);
    float4 rI0 = *(const float4*)pi0;
    float4 rI1 = *(const float4*)(pi0 + 8*ROWSTRIDE);

    // bias -> smem
    float* bs = (float*)smem;
    bs[tid]       = br[blk*CH + tid];
    bs[tid + 256] = bi[blk*CH + tid];

    // W -> smem once: 2048 16B chunks per tensor, rows padded 1024 -> 1088
    {
        const char* wr_src = (const char*)g_wT + (size_t)blk*131072 + (size_t)n0*512;
        const char* wi_src = wr_src + (size_t)NBLK*131072;
        #pragma unroll
        for (int i = 0; i < 8; i++){
            int c = tid + i*256;         // 0..2047
            uint32_t d = (uint32_t)((c >> 6)*1088 + (c & 63)*16);
            cpa16(sb + SMEM_WR + d, wr_src + (size_t)c*16);
            cpa16(sb + SMEM_WI + d, wi_src + (size_t)c*16);
        }
        cp_commit();
    }

    float dr[8][4], di[8][4];
    #pragma unroll
    for (int n = 0; n < 8; n++)
        #pragma unroll
        for (int c = 0; c < 4; c++){ dr[n][c] = 0.f; di[n][c] = 0.f; }

    cp_wait0();
    __syncthreads();                     // the ONLY barrier before epilogue

    // pack slice-0 fragments, then issue slice-1 A loads
    uint32_t far[4], fai[4], fan[4];
    PACK_R(16);
    PACK_I(16);

    uint32_t wro = sb + SMEM_WR + (uint32_t)(g*1088 + t*16);
    uint32_t wio = sb + SMEM_WI + (uint32_t)(g*1088 + t*16);

    // preload W fragments for (j=0, q=0)
    uint32_t wfr[2][4], wfi[2][4];
    lds128(wro, wfr[0]);
    lds128(wio, wfi[0]);

    // slices 0..13: branch-free hot loop (pack j+1, LDG j+2 interleaved)
    #pragma unroll 1
    for (int j = 0; j < 14; j++){
        SLICE_MMA();
        PACK_R((j + 2) * 16);
        PACK_I((j + 2) * 16);
    }
    // slice 14: pack slice 15, no LDG
    SLICE_MMA();
    PACK_ONLY();
    // slice 15: MMAs only
    SLICE_MMA();

    // epilogue: bias + coalesced float2 streaming stores (evict-first)
    float* o_r = out;
    float* o_i = out + OUT_HALF;
    int row0 = m0 + wid*16 + g;
    #pragma unroll
    for (int nn = 0; nn < 8; nn++){
        int cidx = n0 + nn*8 + 2*t;
        size_t col = (size_t)blk*CH + cidx;
        float b0r = bs[cidx], b1r = bs[cidx+1];
        float b0i = bs[256+cidx], b1i = bs[256+cidx+1];
        size_t a0 = (size_t)row0 * ROWSTRIDE + col;
        size_t a1 = (size_t)(row0 + 8) * ROWSTRIDE + col;
        stg_cs_f2(o_r + a0, dr[nn][0] + b0r, dr[nn][1] + b1r);
        stg_cs_f2(o_r + a1, dr[nn][2] + b0r, dr[nn][3] + b1r);
        stg_cs_f2(o_i + a0, di[nn][0] + b0i, di[nn][1] + b1i);
        stg_cs_f2(o_i + a1, di[nn][2] + b0i, di[nn][3] + b1i);
    }
}

// ---------------------------------------------------------------------------
extern "C" void kernel_launch(void* const* d_in, const int* in_sizes, int n_in,
                              void* d_out, int out_size)
{
    const float* real = (const float*)d_in[0];
    const float* imag = (const float*)d_in[1];
    const float* w_r  = (const float*)d_in[2];
    const float* w_i  = (const float*)d_in[3];
    const float* b_r  = (const float*)d_in[4];
    const float* b_i  = (const float*)d_in[5];
    float* out = (float*)d_out;

    cudaFuncSetAttribute(emm_main,
        cudaFuncAttributeMaxDynamicSharedMemorySize, SMEM_ALLOC);

    emm_prep<<<dim3(16, 16), 256>>>(w_r, w_i);
    emm_main<<<dim3(512, 8), 256, SMEM_ALLOC>>>(real, imag, b_r, b_i, out);
}